// round 17
// baseline (speedup 1.0000x reference)
#include <cuda_runtime.h>
#include <cuda_fp16.h>
#include <math.h>
#include <stdint.h>

#define NT    512
#define RB    192
#define AST   264            // A tile k-stride (fp16): 256 + 8 pad
#define WST   40             // W panel k-stride: 32 + 8 pad
#define RSTR  193
#define GRID  152            // persistent: one CTA per SM

// ---- smem layout (bytes) ----
#define OFF_A       0                   // 192*264*2 = 101376 fp16
#define OFF_WP      101376              // 2 stage slots * 40960
#define SLOT_B      40960
#define OFF_W0P     183296              // 256*40*2 = 20480 (resident)
#define OFF_A0      203776              // 192*40*2 = 15360
#define OFF_B0S     219136              // 256 f32
#define OFF_B1S     220160              // 256 f32
#define OFF_BOS     221184              // 192 f32
#define SMEM_BYTES  221952
// rawS (epilogue2): 192*193*4 = 148224 at sm[0], overlaps A+both slots (dead then)

#define PAN1_B 20480
#define PAN2_B 15360
#define STG1_B 40960                    // GEMM1 stage (2 panels)
#define STG2_B 30720                    // GEMM2 stage (2 panels)

// ---- prebuilt fp16 weight panels ----
__device__ __align__(16) __half g_w1[8 * 256 * 40];
__device__ __align__(16) __half g_wo[8 * 192 * 40];
__device__ __align__(16) __half g_w0[256 * 40];     // [W0hi | W0hi | W0lo | 0]

// ---- helpers ----
__device__ __forceinline__ uint32_t smem_u32(const void* p) {
    uint32_t a;
    asm("{ .reg .u64 t; cvta.to.shared.u64 t, %1; cvt.u32.u64 %0, t; }" : "=r"(a) : "l"(p));
    return a;
}
__device__ __forceinline__ void cp16(uint32_t dst, const void* src) {
    asm volatile("cp.async.cg.shared.global [%0], [%1], 16;" :: "r"(dst), "l"(src));
}
#define CP_COMMIT() asm volatile("cp.async.commit_group;")
#define CP_WAIT0()  asm volatile("cp.async.wait_group 0;")

__device__ __forceinline__ void mma16(float* d, uint32_t a0, uint32_t a1, uint32_t a2, uint32_t a3,
                                      uint32_t b0, uint32_t b1) {
    asm volatile("mma.sync.aligned.m16n8k16.row.col.f32.f16.f16.f32 "
                 "{%0,%1,%2,%3}, {%4,%5,%6,%7}, {%8,%9}, {%0,%1,%2,%3};"
                 : "+f"(d[0]), "+f"(d[1]), "+f"(d[2]), "+f"(d[3])
                 : "r"(a0), "r"(a1), "r"(a2), "r"(a3), "r"(b0), "r"(b1));
}
__device__ __forceinline__ void ldsm4(uint32_t& r0, uint32_t& r1, uint32_t& r2, uint32_t& r3,
                                      uint32_t addr) {
    asm volatile("ldmatrix.sync.aligned.m8n8.x4.shared.b16 {%0,%1,%2,%3}, [%4];"
                 : "=r"(r0), "=r"(r1), "=r"(r2), "=r"(r3) : "r"(addr));
}

// ---- fast transcendentals ----
__device__ __forceinline__ float flog1p(float x) {       // x >= 0
    return (x < 1e-2f) ? x * (1.0f - 0.5f * x) : __logf(1.0f + x);
}
__device__ __forceinline__ float softplusf(float v) {
    return fmaxf(v, 0.0f) + flog1p(__expf(-fabsf(v)));
}

// K=32 panel via ldmatrix; 3 m-tiles; B frags double-buffered so the next
// B-LDSM issues behind the current 6 MMAs instead of on the critical path.
template<int NTILES, int ASTRIDE>
__device__ __forceinline__ void panel_compute(uint32_t aLane, uint32_t wLane, float d[3][8][4])
{
    #pragma unroll
    for (int ks = 0; ks < 2; ks++) {
        const uint32_t aK = aLane + ks * 32;
        const uint32_t wK = wLane + ks * 32;
        uint32_t a[3][4];
        #pragma unroll
        for (int mt = 0; mt < 3; mt++)
            ldsm4(a[mt][0], a[mt][1], a[mt][2], a[mt][3], aK + mt * (16 * ASTRIDE * 2));

        uint32_t bA0, bA1, bA2, bA3, bB0, bB1, bB2, bB3;
        ldsm4(bA0, bA1, bA2, bA3, wK);                       // B frag for ntp=0
        #pragma unroll
        for (int ntp = 0; ntp < NTILES / 2; ntp++) {
            if (ntp & 1) {
                if (ntp + 1 < NTILES / 2)
                    ldsm4(bA0, bA1, bA2, bA3, wK + (ntp + 1) * (16 * WST * 2));
                #pragma unroll
                for (int mt = 0; mt < 3; mt++) {
                    mma16(d[mt][2 * ntp],     a[mt][0], a[mt][1], a[mt][2], a[mt][3], bB0, bB1);
                    mma16(d[mt][2 * ntp + 1], a[mt][0], a[mt][1], a[mt][2], a[mt][3], bB2, bB3);
                }
            } else {
                if (ntp + 1 < NTILES / 2)
                    ldsm4(bB0, bB1, bB2, bB3, wK + (ntp + 1) * (16 * WST * 2));
                #pragma unroll
                for (int mt = 0; mt < 3; mt++) {
                    mma16(d[mt][2 * ntp],     a[mt][0], a[mt][1], a[mt][2], a[mt][3], bA0, bA1);
                    mma16(d[mt][2 * ntp + 1], a[mt][0], a[mt][1], a[mt][2], a[mt][3], bA2, bA3);
                }
            }
        }
    }
}

// ---- prep kernels ----
__global__ void prep_w1(const float* __restrict__ W1) {
    int idx = blockIdx.x * blockDim.x + threadIdx.x;      // 81920
    int p = idx / 10240, rem = idx % 10240;
    int n = rem / 40, kk = rem % 40;
    float w = (kk < 32) ? W1[(p * 32 + kk) * 256 + n] : 0.0f;
    g_w1[idx] = __float2half_rn(w);
}
__global__ void prep_wo(const float* __restrict__ Wout) {
    int idx = blockIdx.x * blockDim.x + threadIdx.x;      // 61440
    int p = idx / 7680, rem = idx % 7680;
    int n = rem / 40, kk = rem % 40;
    float w = (kk < 32 && n < 184) ? Wout[(p * 32 + kk) * 184 + n] : 0.0f;
    g_wo[idx] = __float2half_rn(w);
}
__global__ void prep_w0(const float* __restrict__ W0) {
    int idx = blockIdx.x * blockDim.x + threadIdx.x;      // 10240
    int n = idx / 40, kk = idx % 40;
    __half v = __float2half_rn(0.0f);
    if (kk < 16) {
        float w = W0[(kk & 7) * 256 + n];
        v = __float2half_rn(w);
    } else if (kk < 24) {
        float w = W0[(kk - 16) * 256 + n];
        __half h = __float2half_rn(w);
        v = __float2half_rn(w - __half2float(h));
    }
    g_w0[idx] = v;
}

// ---- A0 staging: exact hi/lo split of x2 rows (tid<192, row clamped) ----
__device__ __forceinline__ void stage_a0(char* sm, const float* __restrict__ x,
                                         int row0, int tid, int B) {
    if (tid < RB) {
        const int rr = min(row0 + tid, B - 1);
        const float4* xp = (const float4*)(x + (size_t)rr * 16);
        float4 xc = xp[2], xd = xp[3];
        float xv[8] = {xc.x, xc.y, xc.z, xc.w, xd.x, xd.y, xd.z, xd.w};
        __half2* a0 = (__half2*)(sm + OFF_A0 + tid * 40 * 2);
        #pragma unroll
        for (int j = 0; j < 8; j += 2) {
            __half h0 = __float2half_rn(xv[j]);
            __half h1 = __float2half_rn(xv[j + 1]);
            __half l0 = __float2half_rn(xv[j] - __half2float(h0));
            __half l1 = __float2half_rn(xv[j + 1] - __half2float(h1));
            a0[j / 2]      = __half2(h0, h1);
            a0[4 + j / 2]  = __half2(l0, l1);
            a0[8 + j / 2]  = __half2(h0, h1);
            a0[12 + j / 2] = __half2(__float2half_rn(0.f), __float2half_rn(0.f));
            a0[16 + j / 2] = __half2(__float2half_rn(0.f), __float2half_rn(0.f));
        }
    }
}

// ---- main persistent kernel ----
__global__ void __launch_bounds__(NT, 1)
coupling_hmma_kernel(const float* __restrict__ x,
                     const float* __restrict__ b0,
                     const float* __restrict__ b1,
                     const float* __restrict__ bout,
                     float* __restrict__ out,
                     int B, int nTiles)
{
    extern __shared__ char sm[];
    const int tid = threadIdx.x;
    const int lane = tid & 31;
    const int wid = tid >> 5;
    const int mw = wid & 3, nw = wid >> 2;
    const int qr = lane >> 2, qc = (lane & 3) * 2;
    const uint32_t sm_u32 = smem_u32(sm);
    const uint32_t wp_u32 = sm_u32 + OFF_WP;

    float* b0s = (float*)(sm + OFF_B0S);
    float* b1s = (float*)(sm + OFF_B1S);
    float* bos = (float*)(sm + OFF_BOS);

    const int aRow = (lane & 15);
    const int aKof = (lane >> 4) * 8;
    const int wRow = (lane & 7) + ((lane >> 4) * 8);
    const int wKof = ((lane >> 3) & 1) * 8;
    const uint32_t aLaneA = sm_u32 + OFF_A + (((mw * 48 + aRow) * AST) + aKof) * 2;
    const uint32_t aLane0 = sm_u32 + OFF_A0 + (((mw * 48 + aRow) * 40) + aKof) * 2;
    const uint32_t wRel1 = (((nw * 64 + wRow) * WST) + wKof) * 2;
    const uint32_t wRel2 = (((nw * 48 + wRow) * WST) + wKof) * 2;
    const uint32_t wLane0 = sm_u32 + OFF_W0P + wRel1;

    // ---- one-time prologue: stage0 (slot0), W0P; consts; first A0 ----
    for (int i = tid; i < STG1_B / 16; i += NT)
        cp16(wp_u32 + i * 16, (const char*)g_w1 + i * 16);
    for (int i = tid; i < 1280; i += NT)
        cp16(sm_u32 + OFF_W0P + i * 16, (const char*)g_w0 + i * 16);
    CP_COMMIT();

    for (int i = tid; i < 256; i += NT) { b0s[i] = b0[i]; b1s[i] = b1[i]; }
    for (int i = tid; i < 192; i += NT) bos[i] = (i < 184) ? bout[i] : 0.0f;
    stage_a0(sm, x, blockIdx.x * RB, tid, B);
    __syncthreads();

    // ---- persistent tile loop ----
    for (int t = blockIdx.x; t < nTiles; t += GRID) {
        const int row0 = t * RB;
        const int rowsLeft = min(RB, B - row0);
        const bool more = (t + GRID < nTiles);

        float d[3][8][4];
        #pragma unroll
        for (int mt = 0; mt < 3; mt++)
            #pragma unroll
            for (int nt = 0; nt < 8; nt++)
                #pragma unroll
                for (int i = 0; i < 4; i++) d[mt][nt][i] = 0.0f;

        // ---- GEMM0 (A0 x resident W0P); covers in-flight stage0 load ----
        panel_compute<8, 40>(aLane0, wLane0, d);

        // ---- epilogue0: h0 = relu(d + b0) -> fp16 A tile ----
        #pragma unroll
        for (int mt = 0; mt < 3; mt++) {
            const int r0 = mw * 48 + mt * 16 + qr;
            #pragma unroll
            for (int nt = 0; nt < 8; nt++) {
                const int c = nw * 64 + nt * 8 + qc;
                const float g0 = b0s[c], g1 = b0s[c + 1];
                float v00 = fmaxf(d[mt][nt][0] + g0, 0.f);
                float v01 = fmaxf(d[mt][nt][1] + g1, 0.f);
                float v10 = fmaxf(d[mt][nt][2] + g0, 0.f);
                float v11 = fmaxf(d[mt][nt][3] + g1, 0.f);
                *(__half2*)(sm + OFF_A + ((size_t)r0 * AST + c) * 2) = __floats2half2_rn(v00, v01);
                *(__half2*)(sm + OFF_A + ((size_t)(r0 + 8) * AST + c) * 2) = __floats2half2_rn(v10, v11);
                #pragma unroll
                for (int i = 0; i < 4; i++) d[mt][nt][i] = 0.0f;
            }
        }

        // ---- x2 passthrough (hoisted; latency hides under stage0 wait) ----
        if (tid < 384) {
            const int r = tid >> 1, q = tid & 1;
            if (r < rowsLeft) {
                const size_t gx = (size_t)(row0 + r) * 16 + 8 + q * 4;
                *(float4*)(out + gx) = *(const float4*)(x + gx);
            }
        }

        // ---- stage pipeline: s 0..3 = GEMM1, s 4..7 = GEMM2 (2 slots, wait-all) ----
        for (int s = 0; s < 8; s++) {
            CP_WAIT0();
            __syncthreads();

            if (s == 4) {
                // epilogue1: h1 = relu(d + b1) -> fp16 A tile
                #pragma unroll
                for (int mt = 0; mt < 3; mt++) {
                    const int r0 = mw * 48 + mt * 16 + qr;
                    #pragma unroll
                    for (int nt = 0; nt < 8; nt++) {
                        const int c = nw * 64 + nt * 8 + qc;
                        const float g0 = b1s[c], g1 = b1s[c + 1];
                        float v00 = fmaxf(d[mt][nt][0] + g0, 0.f);
                        float v01 = fmaxf(d[mt][nt][1] + g1, 0.f);
                        float v10 = fmaxf(d[mt][nt][2] + g0, 0.f);
                        float v11 = fmaxf(d[mt][nt][3] + g1, 0.f);
                        *(__half2*)(sm + OFF_A + ((size_t)r0 * AST + c) * 2) = __floats2half2_rn(v00, v01);
                        *(__half2*)(sm + OFF_A + ((size_t)(r0 + 8) * AST + c) * 2) = __floats2half2_rn(v10, v11);
                        #pragma unroll
                        for (int i = 0; i < 4; i++) d[mt][nt][i] = 0.0f;
                    }
                }
                __syncthreads();
            }

            if (s + 1 < 8) {
                const int ns = s + 1;
                uint32_t dst = wp_u32 + (ns & 1) * SLOT_B;
                if (ns < 4) {
                    const char* src = (const char*)g_w1 + (size_t)ns * STG1_B;
                    for (int i = tid; i < STG1_B / 16; i += NT) cp16(dst + i * 16, src + i * 16);
                } else {
                    const char* src = (const char*)g_wo + (size_t)(ns - 4) * STG2_B;
                    for (int i = tid; i < STG2_B / 16; i += NT) cp16(dst + i * 16, src + i * 16);
                }
            }
            CP_COMMIT();

            const uint32_t slot = wp_u32 + (s & 1) * SLOT_B;
            if (s < 4) {
                panel_compute<8, AST>(aLaneA + (2 * s) * 64,     slot + wRel1, d);
                panel_compute<8, AST>(aLaneA + (2 * s + 1) * 64, slot + PAN1_B + wRel1, d);
            } else {
                panel_compute<6, AST>(aLaneA + (2 * s - 8) * 64, slot + wRel2, d);
                panel_compute<6, AST>(aLaneA + (2 * s - 7) * 64, slot + PAN2_B + wRel2, d);
            }
        }
        __syncthreads();   // all GEMM2 A/W reads done

        // ---- epilogue2: raw = d + bout -> smem f32 [192][193] (overlaps A+slots) ----
        float* rawS = (float*)sm;
        #pragma unroll
        for (int mt = 0; mt < 3; mt++) {
            const int r0 = mw * 48 + mt * 16 + qr;
            #pragma unroll
            for (int nt = 0; nt < 6; nt++) {
                const int c = nw * 48 + nt * 8 + qc;
                rawS[r0 * RSTR + c]           = d[mt][nt][0] + bos[c];
                rawS[r0 * RSTR + c + 1]       = d[mt][nt][1] + bos[c + 1];
                rawS[(r0 + 8) * RSTR + c]     = d[mt][nt][2] + bos[c];
                rawS[(r0 + 8) * RSTR + c + 1] = d[mt][nt][3] + bos[c + 1];
            }
        }
        if (more) stage_a0(sm, x, (t + GRID) * RB, tid, B);   // A0 region free
        __syncthreads();   // rawS + next-A0 visible

        // ---- spline: 512 threads x 3 iters, 1 transform each ----
        {
            const float CNST = logf(expf(1.0f - 1e-4f) - 1.0f);
            #pragma unroll 1
            for (int k = 0; k < 3; k++) {
                const int g = k * NT + tid;           // 0..1535
                const int r = g >> 3, tt = g & 7;
                const int grow = row0 + r;
                const bool valid = (r < rowsLeft);
                const float xv = x[(size_t)min(grow, B - 1) * 16 + tt];
                const float* raw = rawS + r * RSTR + tt * 23;

                float rw[8], rh[8];
                #pragma unroll
                for (int c = 0; c < 8; c++) { rw[c] = raw[c]; rh[c] = raw[8 + c]; }

                float m = rw[0];
                #pragma unroll
                for (int c = 1; c < 8; c++) m = fmaxf(m, rw[c]);
                float sum = 0.0f, ew[8];
                #pragma unroll
                for (int c = 0; c < 8; c++) { ew[c] = __expf(rw[c] - m); sum += ew[c]; }
                float inv = __fdividef(1.0f, sum);
                float wdt[8];
                #pragma unroll
                for (int c = 0; c < 8; c++) wdt[c] = 2.0f * (1e-4f + (1.0f - 8e-4f) * ew[c] * inv);

                m = rh[0];
                #pragma unroll
                for (int c = 1; c < 8; c++) m = fmaxf(m, rh[c]);
                sum = 0.0f;
                #pragma unroll
                for (int c = 0; c < 8; c++) { ew[c] = __expf(rh[c] - m); sum += ew[c]; }
                inv = __fdividef(1.0f, sum);
                float hgt[8];
                #pragma unroll
                for (int c = 0; c < 8; c++) hgt[c] = 2.0f * (1e-4f + (1.0f - 8e-4f) * ew[c] * inv);

                float dv[9];
                dv[0] = 1.0f; dv[8] = 1.0f;
                #pragma unroll
                for (int c = 0; c < 7; c++) dv[c + 1] = softplusf(raw[16 + c] + CNST) + 1e-4f;

                const bool mask = (xv <= -0.999f) || (xv >= 0.999f);
                const float xin = mask ? 0.0f : xv;

                // bin search: i=0 always captures (cx0 = -1 <= xin)
                float xk = -1.0f, yk = -1.0f, wk = wdt[0], hk = hgt[0], dk = dv[0], dk1 = dv[1];
                float cx = -1.0f + wdt[0], cy = -1.0f + hgt[0];
                #pragma unroll
                for (int i = 1; i < 8; i++) {
                    if (cx <= xin) { xk = cx; yk = cy; wk = wdt[i]; hk = hgt[i]; dk = dv[i]; dk1 = dv[i + 1]; }
                    cx += wdt[i]; cy += hgt[i];
                }

                const float invwk = __fdividef(1.0f, wk);
                const float sk   = hk * invwk;
                const float eps  = (xin - xk) * invwk;
                const float et   = eps * (1.0f - eps);
                const float e2   = eps * eps;
                const float beta = sk + (dk1 + dk - 2.0f * sk) * et;
                const float alp  = hk * (sk * e2 + dk * et);
                const float y    = mask ? xv : (yk + __fdividef(alp, beta));
                const float ome  = 1.0f - eps;
                float ld = 2.0f * __logf(sk)
                         + __logf(dk1 * e2 + 2.0f * sk * et + dk * ome * ome)
                         - 2.0f * __logf(beta);
                ld = mask ? 0.0f : ld;

                if (valid)
                    out[(size_t)grow * 16 + tt] = y;

                ld += __shfl_xor_sync(0xffffffffu, ld, 1);
                ld += __shfl_xor_sync(0xffffffffu, ld, 2);
                ld += __shfl_xor_sync(0xffffffffu, ld, 4);
                if ((lane & 7) == 0 && valid)
                    out[(size_t)B * 16 + grow] = ld;
            }
        }
        __syncthreads();   // spline rawS reads done -> A + slots free

        // issue next tile's stage0 into slot0 (covered by next GEMM0+epi0)
        if (more) {
            for (int i = tid; i < STG1_B / 16; i += NT)
                cp16(wp_u32 + i * 16, (const char*)g_w1 + i * 16);
        }
        CP_COMMIT();
    }
}

extern "C" void kernel_launch(void* const* d_in, const int* in_sizes, int n_in,
                              void* d_out, int out_size) {
    const float* x    = (const float*)d_in[0];
    const float* W0   = (const float*)d_in[1];
    const float* b0   = (const float*)d_in[2];
    const float* W1   = (const float*)d_in[3];
    const float* b1   = (const float*)d_in[4];
    const float* Wout = (const float*)d_in[5];
    const float* bout = (const float*)d_in[6];
    float* out = (float*)d_out;

    const int B = in_sizes[0] / 16;
    const int nTiles = (B + RB - 1) / RB;

    prep_w1<<<320, 256>>>(W1);
    prep_wo<<<240, 256>>>(Wout);
    prep_w0<<<40, 256>>>(W0);

    cudaFuncSetAttribute(coupling_hmma_kernel,
                         cudaFuncAttributeMaxDynamicSharedMemorySize, SMEM_BYTES);
    coupling_hmma_kernel<<<GRID, NT, SMEM_BYTES>>>(x, b0, b1, bout, out, B, nTiles);
}